// round 15
// baseline (speedup 1.0000x reference)
#include <cuda_runtime.h>
#include <cuda_fp16.h>
#include <cstdint>

// GraphSAGE 2-layer, mean aggregation. Transform-then-aggregate + CSR-gather.
//   y1 = x @ [W1_l; W1_r]^T   (fp16 m16n8k16 mma, fp32 accumulate)
//   h  = relu(gather-mean(y1agg) + b1 + y1root)
//   y2 = h @ [W2_l; W2_r]^T
//   out= gather-mean(y2agg) + b2 + y2root
// This round: kernel-count reduction. detect fused into zero; 3-kernel scan
// replaced by single-kernel decoupled-lookback scan. 8 launches total.
// gemm1 submitted 4th (ncu capture lands on the 4th user launch).

#define MAXN 100000
#define MAXE 1600000
#define DIN 128
#define DH 64
#define DOUT 32

__device__ __align__(16) __half g_y1agg[MAXN * DH];      // [M][64] fp16
__device__ __align__(16) float  g_y1root[MAXN * DH];     // [M][64] fp32
__device__ __align__(16) float  g_h[MAXN * DH];          // [M][64]
__device__ __align__(16) __half g_y2agg[MAXN * DOUT];    // [M][32] fp16
__device__ __align__(16) float  g_y2root[MAXN * DOUT];   // [M][32] fp32
__device__ __align__(16) int    g_adj[MAXE];
__device__ __align__(16) int    g_rowstart[MAXN + 1];
__device__ __align__(16) int    g_degi[MAXN];
__device__ __align__(16) int    g_aggval[512];
__device__ __align__(16) int    g_incval[512];
__device__ volatile int g_sflag[512];
__device__ int g_is64;

// ---------------------------------------------------------------------------
__device__ __forceinline__ unsigned h2bits(float x, float y) {
    __half2 h = __floats2half2_rn(x, y);
    return *(unsigned*)&h;
}
__device__ __forceinline__ void mma_f16(float* c, const unsigned* a,
                                        const unsigned* b) {
    asm volatile(
        "mma.sync.aligned.m16n8k16.row.col.f32.f16.f16.f32 "
        "{%0,%1,%2,%3}, {%4,%5,%6,%7}, {%8,%9}, {%0,%1,%2,%3};"
        : "+f"(c[0]), "+f"(c[1]), "+f"(c[2]), "+f"(c[3])
        : "r"(a[0]), "r"(a[1]), "r"(a[2]), "r"(a[3]), "r"(b[0]), "r"(b[1]));
}
__device__ __forceinline__ void acc8(float* a, uint4 v) {
    float2 f0 = __half22float2(*(__half2*)&v.x);
    float2 f1 = __half22float2(*(__half2*)&v.y);
    float2 f2 = __half22float2(*(__half2*)&v.z);
    float2 f3 = __half22float2(*(__half2*)&v.w);
    a[0] += f0.x; a[1] += f0.y; a[2] += f1.x; a[3] += f1.y;
    a[4] += f2.x; a[5] += f2.y; a[6] += f3.x; a[7] += f3.y;
}

// ---------------------------------------------------------------------------
// Fused: zero g_degi + scan flags; block 0 warps 0-3 also run dtype detect.
// ---------------------------------------------------------------------------
__global__ __launch_bounds__(256) void zero_detect(const int* __restrict__ ei32,
                                                   int nE, int M) {
    int idx = blockIdx.x * blockDim.x + threadIdx.x;
    if (idx < M) g_degi[idx] = 0;
    if (idx < 512) g_sflag[idx] = 0;
    if (blockIdx.x == 0 && threadIdx.x < 128) {
        int n = nE < 128 ? nE : 128;
        int tid = threadIdx.x;
        int bad = (tid < n && ei32[2 * tid + 1] != 0) ? 1 : 0;
        unsigned m = __ballot_sync(0xffffffffu, bad);
        __shared__ unsigned s[4];
        if ((tid & 31) == 0) s[tid >> 5] = m;
        __syncwarp();
        __syncthreads();
        if (tid == 0)
            g_is64 = ((s[0] | s[1] | s[2] | s[3]) == 0u) ? 1 : 0;
    }
}

__global__ __launch_bounds__(256) void decode_kernel(const void* __restrict__ ei,
                                                     int nE) {
    int t = blockIdx.x * blockDim.x + threadIdx.x;
    int e0 = t * 4;
    if (e0 >= nE) return;
    if (g_is64) {
        const long long* p = (const long long*)ei + nE;
#pragma unroll
        for (int i = 0; i < 4; i++)
            if (e0 + i < nE) atomicAdd(&g_degi[(int)p[e0 + i]], 1);
    } else {
        const int* p = (const int*)ei + nE;
        if (e0 + 3 < nE) {
            int4 d = *(const int4*)&p[e0];
            atomicAdd(&g_degi[d.x], 1);
            atomicAdd(&g_degi[d.y], 1);
            atomicAdd(&g_degi[d.z], 1);
            atomicAdd(&g_degi[d.w], 1);
        } else {
            for (int i = 0; i < 4 && e0 + i < nE; i++)
                atomicAdd(&g_degi[p[e0 + i]], 1);
        }
    }
}

// ---------------------------------------------------------------------------
// Single-kernel exclusive scan (decoupled lookback). nB <= 512 blocks, all
// co-resident -> no deadlock. Flags zeroed by zero_detect each replay.
// ---------------------------------------------------------------------------
__global__ __launch_bounds__(256) void scan_fused(int M, int nE) {
    __shared__ int wsum[8];
    __shared__ int sh_pref;
    int tid = threadIdx.x;
    int lane = tid & 31;
    int warp = tid >> 5;
    int bid = blockIdx.x;
    int i = bid * 256 + tid;
    int v = (i < M) ? g_degi[i] : 0;
    int x = v;
#pragma unroll
    for (int off = 1; off < 32; off <<= 1) {
        int t = __shfl_up_sync(0xffffffffu, x, off);
        if (lane >= off) x += t;
    }
    if (lane == 31) wsum[warp] = x;
    __syncthreads();
    if (warp == 0 && lane < 8) {
        int s = wsum[lane];
#pragma unroll
        for (int off = 1; off < 8; off <<= 1) {
            int t = __shfl_up_sync(0xffu, s, off, 8);
            if (lane >= off) s += t;
        }
        wsum[lane] = s;
    }
    __syncthreads();
    int base = (warp > 0) ? wsum[warp - 1] : 0;
    int incl = x + base;
    int total = wsum[7];

    if (tid == 0) {
        if (bid == 0) {
            g_incval[0] = total;
            __threadfence();
            g_sflag[0] = 2;
            sh_pref = 0;
        } else {
            g_aggval[bid] = total;
            __threadfence();
            g_sflag[bid] = 1;
            int pref = 0;
            int j = bid - 1;
            while (true) {
                int f;
                do { f = g_sflag[j]; } while (f == 0);
                __threadfence();
                if (f == 2) { pref += g_incval[j]; break; }
                pref += g_aggval[j];
                j--;
            }
            g_incval[bid] = pref + total;
            __threadfence();
            g_sflag[bid] = 2;
            sh_pref = pref;
        }
    }
    __syncthreads();
    int ex = sh_pref + incl - v;
    if (i < M) g_rowstart[i] = ex;
    if (i == 0) g_rowstart[M] = nE;
}

// Fill CSR: 4 edges per thread; countdown cursor in g_degi.
__global__ __launch_bounds__(256) void csr_fill(const void* __restrict__ ei,
                                                int nE) {
    int t = blockIdx.x * blockDim.x + threadIdx.x;
    int e0 = t * 4;
    if (e0 >= nE) return;
    int src[4], dst[4], n = 0;
    if (g_is64) {
        const long long* ps = (const long long*)ei;
        const long long* pd = ps + nE;
        for (int i = 0; i < 4 && e0 + i < nE; i++) {
            src[i] = (int)ps[e0 + i];
            dst[i] = (int)pd[e0 + i];
            n++;
        }
    } else {
        const int* ps = (const int*)ei;
        const int* pd = ps + nE;
        if (e0 + 3 < nE) {
            int4 s4 = *(const int4*)&ps[e0];
            int4 d4 = *(const int4*)&pd[e0];
            src[0] = s4.x; src[1] = s4.y; src[2] = s4.z; src[3] = s4.w;
            dst[0] = d4.x; dst[1] = d4.y; dst[2] = d4.z; dst[3] = d4.w;
            n = 4;
        } else {
            for (int i = 0; i < 4 && e0 + i < nE; i++) {
                src[i] = ps[e0 + i];
                dst[i] = pd[e0 + i];
                n++;
            }
        }
    }
#pragma unroll
    for (int i = 0; i < 4; i++) {
        if (i < n) {
            int pos = g_rowstart[dst[i]] + atomicSub(&g_degi[dst[i]], 1) - 1;
            g_adj[pos] = src[i];
        }
    }
}

// ---------------------------------------------------------------------------
// GEMM1 (fp16 m16n8k16): [y1agg(fp16) | y1root(fp32)] = X @ [Wa; Wb]^T
// ---------------------------------------------------------------------------
__global__ __launch_bounds__(256) void gemm1(const float* __restrict__ X,
                                             const float* __restrict__ Wa,
                                             const float* __restrict__ Wb,
                                             int M) {
    __shared__ unsigned As[128 * 20];
    __shared__ unsigned Bs[128 * 20];

    const int tid = threadIdx.x;
    const int lane = tid & 31;
    const int warp = tid >> 5;
    const int wm = (warp & 1) * 64;
    const int wn = (warp >> 1) * 32;
    const int m0 = blockIdx.x * 128;

    const int lr = tid >> 1;
    const int lcbase = (tid & 1) * 16;

    float acc[4][4][4];
#pragma unroll
    for (int a = 0; a < 4; a++)
#pragma unroll
        for (int b = 0; b < 4; b++)
#pragma unroll
            for (int f = 0; f < 4; f++) acc[a][b][f] = 0.f;

    for (int k0 = 0; k0 < 128; k0 += 32) {
        {
            int gm = m0 + lr;
#pragma unroll
            for (int i = 0; i < 4; i++) {
                int c = lcbase + i * 4;
                float4 v = make_float4(0.f, 0.f, 0.f, 0.f);
                if (gm < M) v = *(const float4*)&X[(size_t)gm * 128 + k0 + c];
                uint2 t = make_uint2(h2bits(v.x, v.y), h2bits(v.z, v.w));
                *(uint2*)&As[lr * 20 + (c >> 1)] = t;
            }
        }
        {
            const float* w = (lr < 64) ? (Wa + (size_t)lr * 128)
                                       : (Wb + (size_t)(lr - 64) * 128);
#pragma unroll
            for (int i = 0; i < 4; i++) {
                int c = lcbase + i * 4;
                float4 v = *(const float4*)&w[k0 + c];
                uint2 t = make_uint2(h2bits(v.x, v.y), h2bits(v.z, v.w));
                *(uint2*)&Bs[lr * 20 + (c >> 1)] = t;
            }
        }
        __syncthreads();

#pragma unroll
        for (int ks = 0; ks < 2; ks++) {
            const int kc = ks * 8;
            unsigned af[4][4], bf[4][2];
#pragma unroll
            for (int mt = 0; mt < 4; mt++) {
                int r = wm + mt * 16 + (lane >> 2);
                int c = kc + (lane & 3);
                af[mt][0] = As[r * 20 + c];
                af[mt][1] = As[(r + 8) * 20 + c];
                af[mt][2] = As[r * 20 + c + 4];
                af[mt][3] = As[(r + 8) * 20 + c + 4];
            }
#pragma unroll
            for (int nt = 0; nt < 4; nt++) {
                int n = wn + nt * 8 + (lane >> 2);
                bf[nt][0] = Bs[n * 20 + kc + (lane & 3)];
                bf[nt][1] = Bs[n * 20 + kc + (lane & 3) + 4];
            }
#pragma unroll
            for (int mt = 0; mt < 4; mt++)
#pragma unroll
                for (int nt = 0; nt < 4; nt++)
                    mma_f16(acc[mt][nt], af[mt], bf[nt]);
        }
        __syncthreads();
    }

#pragma unroll
    for (int mt = 0; mt < 4; mt++) {
#pragma unroll
        for (int nt = 0; nt < 4; nt++) {
            int row = m0 + wm + mt * 16 + (lane >> 2);
            int col = wn + nt * 8 + (lane & 3) * 2;
            if (col < 64) {
                __half2 h0 = __floats2half2_rn(acc[mt][nt][0], acc[mt][nt][1]);
                __half2 h1 = __floats2half2_rn(acc[mt][nt][2], acc[mt][nt][3]);
                if (row < M)
                    *(__half2*)&g_y1agg[(size_t)row * 64 + col] = h0;
                if (row + 8 < M)
                    *(__half2*)&g_y1agg[(size_t)(row + 8) * 64 + col] = h1;
            } else {
                int rc = col - 64;
                if (row < M)
                    *(float2*)&g_y1root[(size_t)row * 64 + rc] =
                        make_float2(acc[mt][nt][0], acc[mt][nt][1]);
                if (row + 8 < M)
                    *(float2*)&g_y1root[(size_t)(row + 8) * 64 + rc] =
                        make_float2(acc[mt][nt][2], acc[mt][nt][3]);
            }
        }
    }
}

// ---------------------------------------------------------------------------
// GEMM2 (fp16): [y2agg(fp16) | y2root(fp32)] = H @ [Wa(32x64); Wb(32x64)]^T
// ---------------------------------------------------------------------------
__global__ __launch_bounds__(256) void gemm2(const float* __restrict__ Wa,
                                             const float* __restrict__ Wb,
                                             int M) {
    __shared__ unsigned As[128 * 20];
    __shared__ unsigned Bs[64 * 20];

    const int tid = threadIdx.x;
    const int lane = tid & 31;
    const int warp = tid >> 5;
    const int wm = (warp & 1) * 64;
    const int wn = (warp >> 1) * 16;
    const int m0 = blockIdx.x * 128;

    const int lr = tid >> 1;
    const int lcbase = (tid & 1) * 16;

    float acc[4][2][4];
#pragma unroll
    for (int a = 0; a < 4; a++)
#pragma unroll
        for (int b = 0; b < 2; b++)
#pragma unroll
            for (int f = 0; f < 4; f++) acc[a][b][f] = 0.f;

    for (int k0 = 0; k0 < 64; k0 += 32) {
        {
            int gm = m0 + lr;
#pragma unroll
            for (int i = 0; i < 4; i++) {
                int c = lcbase + i * 4;
                float4 v = make_float4(0.f, 0.f, 0.f, 0.f);
                if (gm < M) v = *(const float4*)&g_h[(size_t)gm * 64 + k0 + c];
                uint2 t = make_uint2(h2bits(v.x, v.y), h2bits(v.z, v.w));
                *(uint2*)&As[lr * 20 + (c >> 1)] = t;
            }
        }
        if (lr < 64) {
            const float* w = (lr < 32) ? (Wa + (size_t)lr * 64)
                                       : (Wb + (size_t)(lr - 32) * 64);
#pragma unroll
            for (int i = 0; i < 4; i++) {
                int c = lcbase + i * 4;
                float4 v = *(const float4*)&w[k0 + c];
                uint2 t = make_uint2(h2bits(v.x, v.y), h2bits(v.z, v.w));
                *(uint2*)&Bs[lr * 20 + (c >> 1)] = t;
            }
        }
        __syncthreads();

#pragma unroll
        for (int ks = 0; ks < 2; ks++) {
            const int kc = ks * 8;
            unsigned af[4][4], bf[2][2];
#pragma unroll
            for (int mt = 0; mt < 4; mt++) {
                int r = wm + mt * 16 + (lane >> 2);
                int c = kc + (lane & 3);
                af[mt][0] = As[r * 20 + c];
                af[mt][1] = As[(r + 8) * 20 + c];
                af[mt][2] = As[r * 20 + c + 4];
                af[mt][3] = As[(r + 8) * 20 + c + 4];
            }
#pragma unroll
            for (int nt = 0; nt < 2; nt++) {
                int n = wn + nt * 8 + (lane >> 2);
                bf[nt][0] = Bs[n * 20 + kc + (lane & 3)];
                bf[nt][1] = Bs[n * 20 + kc + (lane & 3) + 4];
            }
#pragma unroll
            for (int mt = 0; mt < 4; mt++)
#pragma unroll
                for (int nt = 0; nt < 2; nt++)
                    mma_f16(acc[mt][nt], af[mt], bf[nt]);
        }
        __syncthreads();
    }

#pragma unroll
    for (int mt = 0; mt < 4; mt++) {
#pragma unroll
        for (int nt = 0; nt < 2; nt++) {
            int row = m0 + wm + mt * 16 + (lane >> 2);
            int col = wn + nt * 8 + (lane & 3) * 2;
            if (col < 32) {
                __half2 h0 = __floats2half2_rn(acc[mt][nt][0], acc[mt][nt][1]);
                __half2 h1 = __floats2half2_rn(acc[mt][nt][2], acc[mt][nt][3]);
                if (row < M)
                    *(__half2*)&g_y2agg[(size_t)row * 32 + col] = h0;
                if (row + 8 < M)
                    *(__half2*)&g_y2agg[(size_t)(row + 8) * 32 + col] = h1;
            } else {
                int rc = col - 32;
                if (row < M)
                    *(float2*)&g_y2root[(size_t)row * 32 + rc] =
                        make_float2(acc[mt][nt][0], acc[mt][nt][1]);
                if (row + 8 < M)
                    *(float2*)&g_y2root[(size_t)(row + 8) * 32 + rc] =
                        make_float2(acc[mt][nt][2], acc[mt][nt][3]);
            }
        }
    }
}

// ---------------------------------------------------------------------------
// gather1: warp per dst. Row = 64 fp16 = 8 uint4. c8 x ns(0..3). fp32 acc.
// ---------------------------------------------------------------------------
__global__ __launch_bounds__(256) void gather1(const float4* __restrict__ b1,
                                               int M) {
    int w = (blockIdx.x * blockDim.x + threadIdx.x) >> 5;
    if (w >= M) return;
    int lane = threadIdx.x & 31;
    int c8 = lane & 7;
    int ns = lane >> 3;
    int beg = g_rowstart[w];
    int end = g_rowstart[w + 1];

    float a[8] = {0.f, 0.f, 0.f, 0.f, 0.f, 0.f, 0.f, 0.f};
    for (int j = beg + ns; j < end; j += 4) {
        int src = __ldg(&g_adj[j]);
        uint4 v = __ldg((const uint4*)g_y1agg + (size_t)src * 8 + c8);
        acc8(a, v);
    }
#pragma unroll
    for (int i = 0; i < 8; i++) {
        a[i] += __shfl_down_sync(0xffffffffu, a[i], 16);
        a[i] += __shfl_down_sync(0xffffffffu, a[i], 8);
    }

    if (ns == 0) {
        float inv = 1.0f / fmaxf((float)(end - beg), 1.0f);
        const float4* root = (const float4*)g_y1root + (size_t)w * 16 + c8 * 2;
        float4 r0 = __ldg(root);
        float4 r1 = __ldg(root + 1);
        float4 b0 = __ldg(&b1[c8 * 2]);
        float4 b1v = __ldg(&b1[c8 * 2 + 1]);
        float4 o0, o1;
        o0.x = fmaxf(fmaf(a[0], inv, b0.x + r0.x), 0.f);
        o0.y = fmaxf(fmaf(a[1], inv, b0.y + r0.y), 0.f);
        o0.z = fmaxf(fmaf(a[2], inv, b0.z + r0.z), 0.f);
        o0.w = fmaxf(fmaf(a[3], inv, b0.w + r0.w), 0.f);
        o1.x = fmaxf(fmaf(a[4], inv, b1v.x + r1.x), 0.f);
        o1.y = fmaxf(fmaf(a[5], inv, b1v.y + r1.y), 0.f);
        o1.z = fmaxf(fmaf(a[6], inv, b1v.z + r1.z), 0.f);
        o1.w = fmaxf(fmaf(a[7], inv, b1v.w + r1.w), 0.f);
        float4* hp = (float4*)g_h + (size_t)w * 16 + c8 * 2;
        hp[0] = o0;
        hp[1] = o1;
    }
}

// ---------------------------------------------------------------------------
// gather2: warp per dst. Row = 32 fp16 = 4 uint4. c4 x ns(0..7).
// ---------------------------------------------------------------------------
__global__ __launch_bounds__(256) void gather2(const float4* __restrict__ b2,
                                               float* __restrict__ out, int M) {
    int w = (blockIdx.x * blockDim.x + threadIdx.x) >> 5;
    if (w >= M) return;
    int lane = threadIdx.x & 31;
    int c4 = lane & 3;
    int ns = lane >> 2;
    int beg = g_rowstart[w];
    int end = g_rowstart[w + 1];

    float a[8] = {0.f, 0.f, 0.f, 0.f, 0.f, 0.f, 0.f, 0.f};
    for (int j = beg + ns; j < end; j += 8) {
        int src = __ldg(&g_adj[j]);
        uint4 v = __ldg((const uint4*)g_y2agg + (size_t)src * 4 + c4);
        acc8(a, v);
    }
#pragma unroll
    for (int i = 0; i < 8; i++) {
        a[i] += __shfl_down_sync(0xffffffffu, a[i], 16);
        a[i] += __shfl_down_sync(0xffffffffu, a[i], 8);
        a[i] += __shfl_down_sync(0xffffffffu, a[i], 4);
    }

    if (ns == 0) {
        float inv = 1.0f / fmaxf((float)(end - beg), 1.0f);
        const float4* root = (const float4*)g_y2root + (size_t)w * 8 + c4 * 2;
        float4 r0 = __ldg(root);
        float4 r1 = __ldg(root + 1);
        float4 b0 = __ldg(&b2[c4 * 2]);
        float4 b1v = __ldg(&b2[c4 * 2 + 1]);
        float4 o0, o1;
        o0.x = fmaf(a[0], inv, b0.x + r0.x);
        o0.y = fmaf(a[1], inv, b0.y + r0.y);
        o0.z = fmaf(a[2], inv, b0.z + r0.z);
        o0.w = fmaf(a[3], inv, b0.w + r0.w);
        o1.x = fmaf(a[4], inv, b1v.x + r1.x);
        o1.y = fmaf(a[5], inv, b1v.y + r1.y);
        o1.z = fmaf(a[6], inv, b1v.z + r1.z);
        o1.w = fmaf(a[7], inv, b1v.w + r1.w);
        float4* op = (float4*)out + (size_t)w * 8 + c4 * 2;
        op[0] = o0;
        op[1] = o1;
    }
}

// ---------------------------------------------------------------------------
static inline int cdiv(int a, int b) { return (a + b - 1) / b; }

extern "C" void kernel_launch(void* const* d_in, const int* in_sizes, int n_in,
                              void* d_out, int out_size) {
    const float* x    = (const float*)d_in[0];
    const void*  ei   = d_in[1];
    const float* W1l  = (const float*)d_in[2];
    const float* b1   = (const float*)d_in[3];
    const float* W1r  = (const float*)d_in[4];
    const float* W2l  = (const float*)d_in[5];
    const float* b2   = (const float*)d_in[6];
    const float* W2r  = (const float*)d_in[7];
    float* out = (float*)d_out;

    const int M  = in_sizes[0] / DIN;   // 100000
    const int nE = in_sizes[1] / 2;     // 1600000
    const int nB = cdiv(M, 256);        // <= 512

    static cudaStream_t s2 = nullptr;
    static cudaEvent_t evFork = nullptr, evJoin = nullptr;
    if (s2 == nullptr) {
        cudaStreamCreateWithFlags(&s2, cudaStreamNonBlocking);
        cudaEventCreateWithFlags(&evFork, cudaEventDisableTiming);
        cudaEventCreateWithFlags(&evJoin, cudaEventDisableTiming);
    }

    // Fork: CSR build on s2, gemm1 on default stream.
    cudaEventRecord(evFork, 0);
    cudaStreamWaitEvent(s2, evFork, 0);

    zero_detect<<<cdiv(M, 256), 256, 0, s2>>>((const int*)ei, nE, M);   // 1
    decode_kernel<<<cdiv(cdiv(nE, 4), 256), 256, 0, s2>>>(ei, nE);      // 2
    scan_fused<<<nB, 256, 0, s2>>>(M, nE);                              // 3
    gemm1<<<cdiv(M, 128), 256>>>(x, W1l, W1r, M);                       // 4 (ncu)
    csr_fill<<<cdiv(cdiv(nE, 4), 256), 256, 0, s2>>>(ei, nE);           // 5

    // Join: gather1 needs CSR (s2) and y1 (stream 0).
    cudaEventRecord(evJoin, s2);
    cudaStreamWaitEvent(0, evJoin, 0);

    gather1<<<cdiv(M * 32, 256), 256>>>((const float4*)b1, M);          // 6
    gemm2<<<cdiv(M, 128), 256>>>(W2l, W2r, M);                          // 7
    gather2<<<cdiv(M * 32, 256), 256>>>((const float4*)b2, out, M);     // 8
}

// round 16
// speedup vs baseline: 1.1965x; 1.1965x over previous
#include <cuda_runtime.h>
#include <cuda_fp16.h>
#include <cstdint>

// GraphSAGE 2-layer, mean aggregation. Transform-then-aggregate + CSR-gather.
//   y1 = x @ [W1_l; W1_r]^T   (fp16 m16n8k16 mma + ldmatrix, fp32 accumulate)
//   h  = relu(gather-mean(y1agg) + b1 + y1root)
//   y2 = h @ [W2_l; W2_r]^T
//   out= gather-mean(y2agg) + b2 + y2root
// R15 lookback scan reverted (single-threaded lookback was ~30us of serial L2
// latency). Fragments now loaded with ldmatrix.x4: 6 LDSM vs 24 LDS.32 per
// k-step (gemm1 was L1-bound at 56%). gemm1 is the 4th launch (ncu capture).

#define MAXN 100000
#define MAXE 1600000
#define DIN 128
#define DH 64
#define DOUT 32

__device__ __align__(16) __half g_y1agg[MAXN * DH];      // [M][64] fp16
__device__ __align__(16) float  g_y1root[MAXN * DH];     // [M][64] fp32
__device__ __align__(16) float  g_h[MAXN * DH];          // [M][64]
__device__ __align__(16) __half g_y2agg[MAXN * DOUT];    // [M][32] fp16
__device__ __align__(16) float  g_y2root[MAXN * DOUT];   // [M][32] fp32
__device__ __align__(16) int    g_adj[MAXE];
__device__ __align__(16) int    g_rowstart[MAXN + 1];
__device__ __align__(16) int    g_degi[MAXN];
__device__ __align__(16) int    g_blocksums[512];
__device__ int g_is64;

// ---------------------------------------------------------------------------
__device__ __forceinline__ unsigned h2bits(float x, float y) {
    __half2 h = __floats2half2_rn(x, y);
    return *(unsigned*)&h;
}
__device__ __forceinline__ void mma_f16(float* c, const unsigned* a,
                                        const unsigned* b) {
    asm volatile(
        "mma.sync.aligned.m16n8k16.row.col.f32.f16.f16.f32 "
        "{%0,%1,%2,%3}, {%4,%5,%6,%7}, {%8,%9}, {%0,%1,%2,%3};"
        : "+f"(c[0]), "+f"(c[1]), "+f"(c[2]), "+f"(c[3])
        : "r"(a[0]), "r"(a[1]), "r"(a[2]), "r"(a[3]), "r"(b[0]), "r"(b[1]));
}
__device__ __forceinline__ void ldsm_x4(unsigned& r0, unsigned& r1,
                                        unsigned& r2, unsigned& r3,
                                        uint32_t addr) {
    asm volatile("ldmatrix.sync.aligned.m8n8.x4.shared.b16 {%0,%1,%2,%3}, [%4];"
                 : "=r"(r0), "=r"(r1), "=r"(r2), "=r"(r3) : "r"(addr));
}
__device__ __forceinline__ uint32_t smem_u32(const void* p) {
    return (uint32_t)__cvta_generic_to_shared(p);
}
__device__ __forceinline__ void acc8(float* a, uint4 v) {
    float2 f0 = __half22float2(*(__half2*)&v.x);
    float2 f1 = __half22float2(*(__half2*)&v.y);
    float2 f2 = __half22float2(*(__half2*)&v.z);
    float2 f3 = __half22float2(*(__half2*)&v.w);
    a[0] += f0.x; a[1] += f0.y; a[2] += f1.x; a[3] += f1.y;
    a[4] += f2.x; a[5] += f2.y; a[6] += f3.x; a[7] += f3.y;
}

// ---------------------------------------------------------------------------
// Fused: zero g_degi; block 0 warps 0-3 run dtype detect.
// ---------------------------------------------------------------------------
__global__ __launch_bounds__(256) void zero_detect(const int* __restrict__ ei32,
                                                   int nE, int M) {
    int idx = blockIdx.x * blockDim.x + threadIdx.x;
    if (idx < M) g_degi[idx] = 0;
    if (blockIdx.x == 0 && threadIdx.x < 128) {
        int n = nE < 128 ? nE : 128;
        int tid = threadIdx.x;
        int bad = (tid < n && ei32[2 * tid + 1] != 0) ? 1 : 0;
        unsigned m = __ballot_sync(0xffffffffu, bad);
        __shared__ unsigned s[4];
        if ((tid & 31) == 0) s[tid >> 5] = m;
        __syncwarp();
        __syncthreads();
        if (tid == 0)
            g_is64 = ((s[0] | s[1] | s[2] | s[3]) == 0u) ? 1 : 0;
    }
}

__global__ __launch_bounds__(256) void decode_kernel(const void* __restrict__ ei,
                                                     int nE) {
    int t = blockIdx.x * blockDim.x + threadIdx.x;
    int e0 = t * 4;
    if (e0 >= nE) return;
    if (g_is64) {
        const long long* p = (const long long*)ei + nE;
#pragma unroll
        for (int i = 0; i < 4; i++)
            if (e0 + i < nE) atomicAdd(&g_degi[(int)p[e0 + i]], 1);
    } else {
        const int* p = (const int*)ei + nE;
        if (e0 + 3 < nE) {
            int4 d = *(const int4*)&p[e0];
            atomicAdd(&g_degi[d.x], 1);
            atomicAdd(&g_degi[d.y], 1);
            atomicAdd(&g_degi[d.z], 1);
            atomicAdd(&g_degi[d.w], 1);
        } else {
            for (int i = 0; i < 4 && e0 + i < nE; i++)
                atomicAdd(&g_degi[p[e0 + i]], 1);
        }
    }
}

// ---------------------------------------------------------------------------
// 3-kernel exclusive scan (shuffle-based) — the proven R14 version.
// ---------------------------------------------------------------------------
__global__ __launch_bounds__(256) void scanA(int M) {
    __shared__ int wsum[8];
    int tid = threadIdx.x;
    int lane = tid & 31;
    int warp = tid >> 5;
    int i = blockIdx.x * 256 + tid;
    int v = (i < M) ? g_degi[i] : 0;
    int x = v;
#pragma unroll
    for (int off = 1; off < 32; off <<= 1) {
        int t = __shfl_up_sync(0xffffffffu, x, off);
        if (lane >= off) x += t;
    }
    if (lane == 31) wsum[warp] = x;
    __syncthreads();
    if (warp == 0 && lane < 8) {
        int s = wsum[lane];
#pragma unroll
        for (int off = 1; off < 8; off <<= 1) {
            int t = __shfl_up_sync(0xffu, s, off, 8);
            if (lane >= off) s += t;
        }
        wsum[lane] = s;
    }
    __syncthreads();
    int base = (warp > 0) ? wsum[warp - 1] : 0;
    int incl = x + base;
    if (i < M) g_rowstart[i] = incl - v;
    if (tid == 255) g_blocksums[blockIdx.x] = incl;
}

__global__ void scanB(int nB) {
    __shared__ int wsum[16];
    int tid = threadIdx.x;
    int lane = tid & 31;
    int warp = tid >> 5;
    int v = (tid < nB) ? g_blocksums[tid] : 0;
    int x = v;
#pragma unroll
    for (int off = 1; off < 32; off <<= 1) {
        int t = __shfl_up_sync(0xffffffffu, x, off);
        if (lane >= off) x += t;
    }
    if (lane == 31) wsum[warp] = x;
    __syncthreads();
    if (warp == 0 && lane < 16) {
        int s = wsum[lane];
#pragma unroll
        for (int off = 1; off < 16; off <<= 1) {
            int t = __shfl_up_sync(0xffffu, s, off, 16);
            if (lane >= off) s += t;
        }
        wsum[lane] = s;
    }
    __syncthreads();
    int base = (warp > 0) ? wsum[warp - 1] : 0;
    if (tid < nB) g_blocksums[tid] = x + base - v;
}

__global__ __launch_bounds__(256) void scanC(int M, int nE) {
    int i = blockIdx.x * 256 + threadIdx.x;
    if (i < M) g_rowstart[i] += g_blocksums[blockIdx.x];
    if (i == 0) g_rowstart[M] = nE;
}

// Fill CSR: 4 edges per thread; countdown cursor in g_degi.
__global__ __launch_bounds__(256) void csr_fill(const void* __restrict__ ei,
                                                int nE) {
    int t = blockIdx.x * blockDim.x + threadIdx.x;
    int e0 = t * 4;
    if (e0 >= nE) return;
    int src[4], dst[4], n = 0;
    if (g_is64) {
        const long long* ps = (const long long*)ei;
        const long long* pd = ps + nE;
        for (int i = 0; i < 4 && e0 + i < nE; i++) {
            src[i] = (int)ps[e0 + i];
            dst[i] = (int)pd[e0 + i];
            n++;
        }
    } else {
        const int* ps = (const int*)ei;
        const int* pd = ps + nE;
        if (e0 + 3 < nE) {
            int4 s4 = *(const int4*)&ps[e0];
            int4 d4 = *(const int4*)&pd[e0];
            src[0] = s4.x; src[1] = s4.y; src[2] = s4.z; src[3] = s4.w;
            dst[0] = d4.x; dst[1] = d4.y; dst[2] = d4.z; dst[3] = d4.w;
            n = 4;
        } else {
            for (int i = 0; i < 4 && e0 + i < nE; i++) {
                src[i] = ps[e0 + i];
                dst[i] = pd[e0 + i];
                n++;
            }
        }
    }
#pragma unroll
    for (int i = 0; i < 4; i++) {
        if (i < n) {
            int pos = g_rowstart[dst[i]] + atomicSub(&g_degi[dst[i]], 1) - 1;
            g_adj[pos] = src[i];
        }
    }
}

// ---------------------------------------------------------------------------
// GEMM1 (fp16 m16n8k16 + ldmatrix): [y1agg(fp16)|y1root(fp32)] = X @ [Wa;Wb]^T
// BM=128, BN=128, BK=32 floats (16 half2), 8 warps, warp tile 64x32.
// smem rows: 20 half2 (16 data + 4 pad) -> 20r mod 32 permutes: LDSM
// conflict-free. Per k16 step: 4+2 ldmatrix.x4 instead of 24 LDS.32.
// ---------------------------------------------------------------------------
__global__ __launch_bounds__(256) void gemm1(const float* __restrict__ X,
                                             const float* __restrict__ Wa,
                                             const float* __restrict__ Wb,
                                             int M) {
    __shared__ unsigned As[128 * 20];   // half2 bits
    __shared__ unsigned Bs[128 * 20];

    const int tid = threadIdx.x;
    const int lane = tid & 31;
    const int warp = tid >> 5;
    const int wm = (warp & 1) * 64;
    const int wn = (warp >> 1) * 32;
    const int m0 = blockIdx.x * 128;

    const int lr = tid >> 1;
    const int lcbase = (tid & 1) * 16;

    const uint32_t AsAddr = smem_u32(As);
    const uint32_t BsAddr = smem_u32(Bs);
    const int li = lane >> 3;           // ldmatrix matrix index 0..3
    const int lrr = lane & 7;           // ldmatrix row within matrix

    float acc[4][4][4];
#pragma unroll
    for (int a = 0; a < 4; a++)
#pragma unroll
        for (int b = 0; b < 4; b++)
#pragma unroll
            for (int f = 0; f < 4; f++) acc[a][b][f] = 0.f;

    for (int k0 = 0; k0 < 128; k0 += 32) {
        {
            int gm = m0 + lr;
#pragma unroll
            for (int i = 0; i < 4; i++) {
                int c = lcbase + i * 4;
                float4 v = make_float4(0.f, 0.f, 0.f, 0.f);
                if (gm < M) v = *(const float4*)&X[(size_t)gm * 128 + k0 + c];
                uint2 t = make_uint2(h2bits(v.x, v.y), h2bits(v.z, v.w));
                *(uint2*)&As[lr * 20 + (c >> 1)] = t;
            }
        }
        {
            const float* w = (lr < 64) ? (Wa + (size_t)lr * 128)
                                       : (Wb + (size_t)(lr - 64) * 128);
#pragma unroll
            for (int i = 0; i < 4; i++) {
                int c = lcbase + i * 4;
                float4 v = *(const float4*)&w[k0 + c];
                uint2 t = make_uint2(h2bits(v.x, v.y), h2bits(v.z, v.w));
                *(uint2*)&Bs[lr * 20 + (c >> 1)] = t;
            }
        }
        __syncthreads();

#pragma unroll
        for (int ks = 0; ks < 2; ks++) {
            const int kc = ks * 8;      // half2 offset
            unsigned af[4][4], bf[4][2];
            // A: 4 ldmatrix.x4 (matrices: rows lo/hi x k lo/hi)
#pragma unroll
            for (int mt = 0; mt < 4; mt++) {
                int arow = wm + mt * 16 + (li & 1) * 8 + lrr;
                int ch2 = kc + (li >> 1) * 4;
                ldsm_x4(af[mt][0], af[mt][1], af[mt][2], af[mt][3],
                        AsAddr + (arow * 20 + ch2) * 4);
            }
            // B: 2 ldmatrix.x4, each covering 2 n-tiles x (k lo/hi)
#pragma unroll
            for (int ntp = 0; ntp < 2; ntp++) {
                int nrow = wn + (ntp * 2 + (li >> 1)) * 8 + lrr;
                int ch2 = kc + (li & 1) * 4;
                ldsm_x4(bf[ntp * 2][0], bf[ntp * 2][1],
                        bf[ntp * 2 + 1][0], bf[ntp * 2 + 1][1],
                        BsAddr + (nrow * 20 + ch2) * 4);
            }
#pragma unroll
            for (int mt = 0; mt < 4; mt++)
#pragma unroll
                for (int nt = 0; nt < 4; nt++)
                    mma_f16(acc[mt][nt], af[mt], bf[nt]);
        }
        __syncthreads();
    }

#pragma unroll
    for (int mt = 0; mt < 4; mt++) {
#pragma unroll
        for (int nt = 0; nt < 4; nt++) {
            int row = m0 + wm + mt * 16 + (lane >> 2);
            int col = wn + nt * 8 + (lane & 3) * 2;
            if (col < 64) {
                __half2 h0 = __floats2half2_rn(acc[mt][nt][0], acc[mt][nt][1]);
                __half2 h1 = __floats2half2_rn(acc[mt][nt][2], acc[mt][nt][3]);
                if (row < M)
                    *(__half2*)&g_y1agg[(size_t)row * 64 + col] = h0;
                if (row + 8 < M)
                    *(__half2*)&g_y1agg[(size_t)(row + 8) * 64 + col] = h1;
            } else {
                int rc = col - 64;
                if (row < M)
                    *(float2*)&g_y1root[(size_t)row * 64 + rc] =
                        make_float2(acc[mt][nt][0], acc[mt][nt][1]);
                if (row + 8 < M)
                    *(float2*)&g_y1root[(size_t)(row + 8) * 64 + rc] =
                        make_float2(acc[mt][nt][2], acc[mt][nt][3]);
            }
        }
    }
}

// ---------------------------------------------------------------------------
// GEMM2 (fp16 + ldmatrix): [y2agg(fp16) | y2root(fp32)] = H @ [Wa; Wb]^T
// ---------------------------------------------------------------------------
__global__ __launch_bounds__(256) void gemm2(const float* __restrict__ Wa,
                                             const float* __restrict__ Wb,
                                             int M) {
    __shared__ unsigned As[128 * 20];
    __shared__ unsigned Bs[64 * 20];

    const int tid = threadIdx.x;
    const int lane = tid & 31;
    const int warp = tid >> 5;
    const int wm = (warp & 1) * 64;
    const int wn = (warp >> 1) * 16;
    const int m0 = blockIdx.x * 128;

    const int lr = tid >> 1;
    const int lcbase = (tid & 1) * 16;

    const uint32_t AsAddr = smem_u32(As);
    const uint32_t BsAddr = smem_u32(Bs);
    const int li = lane >> 3;
    const int lrr = lane & 7;

    float acc[4][2][4];
#pragma unroll
    for (int a = 0; a < 4; a++)
#pragma unroll
        for (int b = 0; b < 2; b++)
#pragma unroll
            for (int f = 0; f < 4; f++) acc[a][b][f] = 0.f;

    for (int k0 = 0; k0 < 64; k0 += 32) {
        {
            int gm = m0 + lr;
#pragma unroll
            for (int i = 0; i < 4; i++) {
                int c = lcbase + i * 4;
                float4 v = make_float4(0.f, 0.f, 0.f, 0.f);
                if (gm < M) v = *(const float4*)&g_h[(size_t)gm * 64 + k0 + c];
                uint2 t = make_uint2(h2bits(v.x, v.y), h2bits(v.z, v.w));
                *(uint2*)&As[lr * 20 + (c >> 1)] = t;
            }
        }
        if (lr < 64) {
            const float* w = (lr < 32) ? (Wa + (size_t)lr * 64)
                                       : (Wb + (size_t)(lr - 32) * 64);
#pragma unroll
            for (int i = 0; i < 4; i++) {
                int c = lcbase + i * 4;
                float4 v = *(const float4*)&w[k0 + c];
                uint2 t = make_uint2(h2bits(v.x, v.y), h2bits(v.z, v.w));
                *(uint2*)&Bs[lr * 20 + (c >> 1)] = t;
            }
        }
        __syncthreads();

#pragma unroll
        for (int ks = 0; ks < 2; ks++) {
            const int kc = ks * 8;
            unsigned af[4][4], bf[2][2];
#pragma unroll
            for (int mt = 0; mt < 4; mt++) {
                int arow = wm + mt * 16 + (li & 1) * 8 + lrr;
                int ch2 = kc + (li >> 1) * 4;
                ldsm_x4(af[mt][0], af[mt][1], af[mt][2], af[mt][3],
                        AsAddr + (arow * 20 + ch2) * 4);
            }
            {
                int nrow = wn + (li >> 1) * 8 + lrr;
                int ch2 = kc + (li & 1) * 4;
                ldsm_x4(bf[0][0], bf[0][1], bf[1][0], bf[1][1],
                        BsAddr + (nrow * 20 + ch2) * 4);
            }
#pragma unroll
            for (int mt = 0; mt < 4; mt++)
#pragma unroll
                for (int nt = 0; nt < 2; nt++)
                    mma_f16(acc[mt][nt], af[mt], bf[nt]);
        }
        __syncthreads();
    }

#pragma unroll
    for (int mt = 0; mt < 4; mt++) {
#pragma unroll
        for (int nt = 0; nt < 2; nt++) {
            int row = m0 + wm + mt * 16 + (lane >> 2);
            int col = wn + nt * 8 + (lane & 3) * 2;
            if (col < 32) {
                __half2 h0 = __floats2half2_rn(acc[mt][nt][0], acc[mt][nt][1]);
                __half2 h1 = __floats2half2_rn(acc[mt][nt][2], acc[mt][nt][3]);
                if (row < M)
                    *(__half2*)&g_y2agg[(size_t)row * 32 + col] = h0;
                if (row + 8 < M)
                    *(__half2*)&g_y2agg[(size_t)(row + 8) * 32 + col] = h1;
            } else {
                int rc = col - 32;
                if (row < M)
                    *(float2*)&g_y2root[(size_t)row * 32 + rc] =
                        make_float2(acc[mt][nt][0], acc[mt][nt][1]);
                if (row + 8 < M)
                    *(float2*)&g_y2root[(size_t)(row + 8) * 32 + rc] =
                        make_float2(acc[mt][nt][2], acc[mt][nt][3]);
            }
        }
    }
}

// ---------------------------------------------------------------------------
// gather1: warp per dst. Row = 64 fp16 = 8 uint4. c8 x ns(0..3). fp32 acc.
// ---------------------------------------------------------------------------
__global__ __launch_bounds__(256) void gather1(const float4* __restrict__ b1,
                                               int M) {
    int w = (blockIdx.x * blockDim.x + threadIdx.x) >> 5;
    if (w >= M) return;
    int lane = threadIdx.x & 31;
    int c8 = lane & 7;
    int ns = lane >> 3;
    int beg = g_rowstart[w];
    int end = g_rowstart[w + 1];

    float a[8] = {0.f, 0.f, 0.f, 0.f, 0.f, 0.f, 0.f, 0.f};
    for (int j = beg + ns; j < end; j += 4) {
        int src = __ldg(&g_adj[j]);
        uint4 v = __ldg((const uint4*)g_y1agg + (size_t)src * 8 + c8);
        acc8(a, v);
    }
#pragma unroll
    for (int i = 0; i < 8; i++) {
        a[i] += __shfl_down_sync(0xffffffffu, a[i], 16);
        a[i] += __shfl_down_sync(0xffffffffu, a[i], 8);
    }

    if (ns == 0) {
        float inv = 1.0f / fmaxf((float)(end - beg), 1.0f);
        const float4* root = (const float4*)g_y1root + (size_t)w * 16 + c8 * 2;
        float4 r0 = __ldg(root);
        float4 r1 = __ldg(root + 1);
        float4 b0 = __ldg(&b1[c8 * 2]);
        float4 b1v = __ldg(&b1[c8 * 2 + 1]);
        float4 o0, o1;
        o0.x = fmaxf(fmaf(a[0], inv, b0.x + r0.x), 0.f);
        o0.y = fmaxf(fmaf(a[1], inv, b0.y + r0.y), 0.f);
        o0.z = fmaxf(fmaf(a[2], inv, b0.z + r0.z), 0.f);
        o0.w = fmaxf(fmaf(a[3], inv, b0.w + r0.w), 0.f);
        o1.x = fmaxf(fmaf(a[4], inv, b1v.x + r1.x), 0.f);
        o1.y = fmaxf(fmaf(a[5], inv, b1v.y + r1.y), 0.f);
        o1.z = fmaxf(fmaf(a[6], inv, b1v.z + r1.z), 0.f);
        o1.w = fmaxf(fmaf(a[7], inv, b1v.w + r1.w), 0.f);
        float4* hp = (float4*)g_h + (size_t)w * 16 + c8 * 2;
        hp[0] = o0;
        hp[1] = o1;
    }
}

// ---------------------------------------------------------------------------
// gather2: warp per dst. Row = 32 fp16 = 4 uint4. c4 x ns(0..7).
// ---------------------------------------------------------------------------
__global__ __launch_bounds__(256) void gather2(const float4* __restrict__ b2,
                                               float* __restrict__ out, int M) {
    int w = (blockIdx.x * blockDim.x + threadIdx.x) >> 5;
    if (w >= M) return;
    int lane = threadIdx.x & 31;
    int c4 = lane & 3;
    int ns = lane >> 2;
    int beg = g_rowstart[w];
    int end = g_rowstart[w + 1];

    float a[8] = {0.f, 0.f, 0.f, 0.f, 0.f, 0.f, 0.f, 0.f};
    for (int j = beg + ns; j < end; j += 8) {
        int src = __ldg(&g_adj[j]);
        uint4 v = __ldg((const uint4*)g_y2agg + (size_t)src * 4 + c4);
        acc8(a, v);
    }
#pragma unroll
    for (int i = 0; i < 8; i++) {
        a[i] += __shfl_down_sync(0xffffffffu, a[i], 16);
        a[i] += __shfl_down_sync(0xffffffffu, a[i], 8);
        a[i] += __shfl_down_sync(0xffffffffu, a[i], 4);
    }

    if (ns == 0) {
        float inv = 1.0f / fmaxf((float)(end - beg), 1.0f);
        const float4* root = (const float4*)g_y2root + (size_t)w * 8 + c4 * 2;
        float4 r0 = __ldg(root);
        float4 r1 = __ldg(root + 1);
        float4 b0 = __ldg(&b2[c4 * 2]);
        float4 b1v = __ldg(&b2[c4 * 2 + 1]);
        float4 o0, o1;
        o0.x = fmaf(a[0], inv, b0.x + r0.x);
        o0.y = fmaf(a[1], inv, b0.y + r0.y);
        o0.z = fmaf(a[2], inv, b0.z + r0.z);
        o0.w = fmaf(a[3], inv, b0.w + r0.w);
        o1.x = fmaf(a[4], inv, b1v.x + r1.x);
        o1.y = fmaf(a[5], inv, b1v.y + r1.y);
        o1.z = fmaf(a[6], inv, b1v.z + r1.z);
        o1.w = fmaf(a[7], inv, b1v.w + r1.w);
        float4* op = (float4*)out + (size_t)w * 8 + c4 * 2;
        op[0] = o0;
        op[1] = o1;
    }
}

// ---------------------------------------------------------------------------
static inline int cdiv(int a, int b) { return (a + b - 1) / b; }

extern "C" void kernel_launch(void* const* d_in, const int* in_sizes, int n_in,
                              void* d_out, int out_size) {
    const float* x    = (const float*)d_in[0];
    const void*  ei   = d_in[1];
    const float* W1l  = (const float*)d_in[2];
    const float* b1   = (const float*)d_in[3];
    const float* W1r  = (const float*)d_in[4];
    const float* W2l  = (const float*)d_in[5];
    const float* b2   = (const float*)d_in[6];
    const float* W2r  = (const float*)d_in[7];
    float* out = (float*)d_out;

    const int M  = in_sizes[0] / DIN;   // 100000
    const int nE = in_sizes[1] / 2;     // 1600000
    const int nB = cdiv(M, 256);        // <= 512

    static cudaStream_t s2 = nullptr;
    static cudaEvent_t evFork = nullptr, evJoin = nullptr;
    if (s2 == nullptr) {
        cudaStreamCreateWithFlags(&s2, cudaStreamNonBlocking);
        cudaEventCreateWithFlags(&evFork, cudaEventDisableTiming);
        cudaEventCreateWithFlags(&evJoin, cudaEventDisableTiming);
    }

    // Fork: CSR build on s2, gemm1 on default stream.
    cudaEventRecord(evFork, 0);
    cudaStreamWaitEvent(s2, evFork, 0);

    zero_detect<<<cdiv(M, 256), 256, 0, s2>>>((const int*)ei, nE, M);   // 1
    decode_kernel<<<cdiv(cdiv(nE, 4), 256), 256, 0, s2>>>(ei, nE);      // 2
    scanA<<<nB, 256, 0, s2>>>(M);                                       // 3
    gemm1<<<cdiv(M, 128), 256>>>(x, W1l, W1r, M);                       // 4 (ncu)
    scanB<<<1, 512, 0, s2>>>(nB);                                       // 5
    scanC<<<nB, 256, 0, s2>>>(M, nE);                                   // 6
    csr_fill<<<cdiv(cdiv(nE, 4), 256), 256, 0, s2>>>(ei, nE);           // 7

    // Join: gather1 needs CSR (s2) and y1 (stream 0).
    cudaEventRecord(evJoin, s2);
    cudaStreamWaitEvent(0, evJoin, 0);

    gather1<<<cdiv(M * 32, 256), 256>>>((const float4*)b1, M);          // 8
    gemm2<<<cdiv(M, 128), 256>>>(W2l, W2r, M);                          // 9
    gather2<<<cdiv(M * 32, 256), 256>>>((const float4*)b2, out, M);     // 10
}